// round 15
// baseline (speedup 1.0000x reference)
#include <cuda_runtime.h>
#include <cuda_fp16.h>
#include <mma.h>

using namespace nvcuda;

#define D       128
#define D4      32
#define CAP     128         // bucket capacity; Poisson(32) => P(deg>128) ~ 1e-40
#define N_MAX   100000
#define E_MAX   3200000
#define EPSV    1e-5f

#define SAPAD   136         // half stride for smem tiles (272B: conflict-free ldmatrix)
#define SHPAD   132         // float stride for fp32 result tile

// ---------------- scratch (static device globals; zero-initialized) --------
__device__ int    g_cnt[N_MAX];        // self-cleaned by gather each call
__device__ int    g_slot[(size_t)N_MAX * CAP];
__device__ __half g_featH[(size_t)N_MAX * D];
__device__ __half g_meanH[(size_t)N_MAX * D];
__device__ __half g_WH[D * D];
__device__ __half g_hH[(size_t)N_MAX * D];
__device__ float  g_colsum[D];         // zeroed by build tail block each call
__device__ float  g_colsum2[D];

// ---------------- 1. fused build: bucket scatter + feat->fp16 + W->fp16 ----
//                     + colsum zeroing (tail block)
__global__ void build_kernel(const int* __restrict__ src,
                             const int* __restrict__ dst, int e,
                             const float4* __restrict__ feat, int tot8,
                             const float4* __restrict__ W,
                             int scatB, int halfB, int wB) {
    int b = blockIdx.x, tid = threadIdx.x;
    if (b < scatB) {
        int base = (b * 256 + tid) * 4;
        if (base + 3 < e) {
            int4 d = *(const int4*)(dst + base);
            int4 s = *(const int4*)(src + base);
            int p;
            p = atomicAdd(&g_cnt[d.x], 1); if (p < CAP) g_slot[(size_t)d.x * CAP + p] = s.x;
            p = atomicAdd(&g_cnt[d.y], 1); if (p < CAP) g_slot[(size_t)d.y * CAP + p] = s.y;
            p = atomicAdd(&g_cnt[d.z], 1); if (p < CAP) g_slot[(size_t)d.z * CAP + p] = s.z;
            p = atomicAdd(&g_cnt[d.w], 1); if (p < CAP) g_slot[(size_t)d.w * CAP + p] = s.w;
        } else {
            for (int j = base; j < e; j++) {
                int dd = dst[j];
                int p = atomicAdd(&g_cnt[dd], 1);
                if (p < CAP) g_slot[(size_t)dd * CAP + p] = src[j];
            }
        }
    } else if (b < scatB + halfB) {
        int i = (b - scatB) * 256 + tid;            // one per 8 floats
        if (i < tot8) {
            float4 a = feat[2 * i], c = feat[2 * i + 1];
            __half2 h0 = __floats2half2_rn(a.x, a.y);
            __half2 h1 = __floats2half2_rn(a.z, a.w);
            __half2 h2 = __floats2half2_rn(c.x, c.y);
            __half2 h3 = __floats2half2_rn(c.z, c.w);
            uint4 o;
            o.x = *(unsigned*)&h0; o.y = *(unsigned*)&h1;
            o.z = *(unsigned*)&h2; o.w = *(unsigned*)&h3;
            ((uint4*)g_featH)[i] = o;
        }
    } else if (b < scatB + halfB + wB) {
        int i = (b - scatB - halfB) * 256 + tid;    // one per 8 W floats
        if (i < D * D / 8) {
            float4 a = W[2 * i], c = W[2 * i + 1];
            __half2 h0 = __floats2half2_rn(a.x, a.y);
            __half2 h1 = __floats2half2_rn(a.z, a.w);
            __half2 h2 = __floats2half2_rn(c.x, c.y);
            __half2 h3 = __floats2half2_rn(c.z, c.w);
            uint4 o;
            o.x = *(unsigned*)&h0; o.y = *(unsigned*)&h1;
            o.z = *(unsigned*)&h2; o.w = *(unsigned*)&h3;
            ((uint4*)g_WH)[i] = o;
        }
    } else {
        if (tid < D) { g_colsum[tid] = 0.f; g_colsum2[tid] = 0.f; }
    }
}

// ---------------- 2. per-node mean aggregation (1 warp/node, 2 edges/iter) --
// 16 lanes cover one 256B feature row with uint4 loads; lanes 0-15 take even
// edges, 16-31 odd edges; halves combined with shfl_xor(16).
// Self-cleans g_cnt for the next graph replay.
__global__ void gather_mean_kernel(int n) {
    int gw   = (blockIdx.x * blockDim.x + threadIdx.x) >> 5;
    int lane = threadIdx.x & 31;
    if (gw >= n) return;
    int deg = g_cnt[gw];
    if (lane == 0) g_cnt[gw] = 0;                  // reset for next call
    if (deg > CAP) deg = CAP;
    size_t base = (size_t)gw * CAP;
    int half = lane >> 4;           // edge parity
    int sub  = lane & 15;           // position within row (16 x 16B)
    const uint4* F = (const uint4*)g_featH;    // 16 uint4 per row
    float a0=0.f,a1=0.f,a2=0.f,a3=0.f,a4=0.f,a5=0.f,a6=0.f,a7=0.f;
    for (int i = half; i < deg; i += 2) {
        int sr = g_slot[base + i];
        uint4 v = __ldg(&F[(size_t)sr * 16 + sub]);
        float2 f0 = __half22float2(*(__half2*)&v.x);
        float2 f1 = __half22float2(*(__half2*)&v.y);
        float2 f2 = __half22float2(*(__half2*)&v.z);
        float2 f3 = __half22float2(*(__half2*)&v.w);
        a0 += f0.x; a1 += f0.y; a2 += f1.x; a3 += f1.y;
        a4 += f2.x; a5 += f2.y; a6 += f3.x; a7 += f3.y;
    }
    a0 += __shfl_xor_sync(0xffffffffu, a0, 16);
    a1 += __shfl_xor_sync(0xffffffffu, a1, 16);
    a2 += __shfl_xor_sync(0xffffffffu, a2, 16);
    a3 += __shfl_xor_sync(0xffffffffu, a3, 16);
    a4 += __shfl_xor_sync(0xffffffffu, a4, 16);
    a5 += __shfl_xor_sync(0xffffffffu, a5, 16);
    a6 += __shfl_xor_sync(0xffffffffu, a6, 16);
    a7 += __shfl_xor_sync(0xffffffffu, a7, 16);
    if (half == 0) {
        float inv = 1.f / fmaxf((float)deg, 1.f);
        __half2 o0 = __floats2half2_rn(a0 * inv, a1 * inv);
        __half2 o1 = __floats2half2_rn(a2 * inv, a3 * inv);
        __half2 o2 = __floats2half2_rn(a4 * inv, a5 * inv);
        __half2 o3 = __floats2half2_rn(a6 * inv, a7 * inv);
        uint4 o;
        o.x = *(unsigned*)&o0; o.y = *(unsigned*)&o1;
        o.z = *(unsigned*)&o2; o.w = *(unsigned*)&o3;
        ((uint4*)g_meanH)[(size_t)gw * 16 + sub] = o;
    }
}

// ---------------- 3. wmma GEMM h = mean @ W + b, fused stats, fp16 h out ----
// block = 256 thr (8 warps), tile = 128 rows x 128 cols.
// warp w: rows (w>>1)*32 .. +32, cols (w&1)*64 .. +64 -> 2x4 accumulator frags.
__global__ void __launch_bounds__(256) gemm_kernel(const float* __restrict__ bias, int n) {
    extern __shared__ char smem[];
    __half* sW = (__half*)smem;                           // 128 x SAPAD (34816 B)
    __half* sA = (__half*)(smem + 34816);                 // 128 x SAPAD (34816 B)
    float*  sH = (float*)smem;                            // 128 x SHPAD fp32 (67584 B, aliases)
    float*  s_sum  = (float*)(smem + 69632);
    float*  s_sum2 = (float*)(smem + 69632 + 512);

    int tid = threadIdx.x;
    int row0 = blockIdx.x * 128;

    #pragma unroll
    for (int t = tid; t < 128 * 16; t += 256) {
        int r = t >> 4, c = t & 15;
        ((uint4*)(sW + r * SAPAD))[c] = ((const uint4*)g_WH)[r * 16 + c];
    }
    uint4 z4; z4.x = z4.y = z4.z = z4.w = 0u;
    #pragma unroll
    for (int t = tid; t < 128 * 16; t += 256) {
        int r = t >> 4, c = t & 15;
        ((uint4*)(sA + r * SAPAD))[c] =
            (row0 + r < n) ? ((const uint4*)g_meanH)[(size_t)(row0 + r) * 16 + c] : z4;
    }
    if (tid < D) { s_sum[tid] = 0.f; s_sum2[tid] = 0.f; }
    __syncthreads();

    int wid = tid >> 5;
    int wr = wid >> 1;                                    // 0..3 -> 32-row strip
    int wc = wid & 1;                                     // 0..1 -> 64-col half
    wmma::fragment<wmma::accumulator, 16, 16, 16, float> acc[2][4];
    #pragma unroll
    for (int i = 0; i < 2; i++)
        #pragma unroll
        for (int j = 0; j < 4; j++) wmma::fill_fragment(acc[i][j], 0.f);

    #pragma unroll
    for (int k = 0; k < D; k += 16) {
        wmma::fragment<wmma::matrix_a, 16, 16, 16, __half, wmma::row_major> fa[2];
        #pragma unroll
        for (int i = 0; i < 2; i++)
            wmma::load_matrix_sync(fa[i], sA + (wr * 32 + i * 16) * SAPAD + k, SAPAD);
        #pragma unroll
        for (int j = 0; j < 4; j++) {
            wmma::fragment<wmma::matrix_b, 16, 16, 16, __half, wmma::row_major> fb;
            wmma::load_matrix_sync(fb, sW + k * SAPAD + wc * 64 + j * 16, SAPAD);
            wmma::mma_sync(acc[0][j], fa[0], fb, acc[0][j]);
            wmma::mma_sync(acc[1][j], fa[1], fb, acc[1][j]);
        }
    }
    __syncthreads();                                      // all reads of sW/sA done
    #pragma unroll
    for (int i = 0; i < 2; i++)
        #pragma unroll
        for (int j = 0; j < 4; j++)
            wmma::store_matrix_sync(sH + (wr * 32 + i * 16) * SHPAD + wc * 64 + j * 16,
                                    acc[i][j], SHPAD, wmma::mem_row_major);
    __syncthreads();

    // epilogue: 256 threads, each handles 16 rows x 4 cols
    int cg = tid & 31, rg = tid >> 5;                     // rg 0..7
    float4 bb = ((const float4*)bias)[cg];
    float ls0=0.f, ls1=0.f, ls2=0.f, ls3=0.f;
    float lq0=0.f, lq1=0.f, lq2=0.f, lq3=0.f;
    #pragma unroll
    for (int i = 0; i < 16; i++) {
        int r = row0 + rg * 16 + i;
        if (r < n) {
            float4 h = *(float4*)&sH[(rg * 16 + i) * SHPAD + cg * 4];
            float x0 = h.x + bb.x, x1 = h.y + bb.y, x2 = h.z + bb.z, x3 = h.w + bb.w;
            ls0 += x0; ls1 += x1; ls2 += x2; ls3 += x3;
            lq0 += x0*x0; lq1 += x1*x1; lq2 += x2*x2; lq3 += x3*x3;
            __half2 p0 = __floats2half2_rn(x0, x1);
            __half2 p1 = __floats2half2_rn(x2, x3);
            uint2 o; o.x = *(unsigned*)&p0; o.y = *(unsigned*)&p1;
            ((uint2*)g_hH)[(size_t)r * 32 + cg] = o;
        }
    }
    atomicAdd(&s_sum[4*cg+0], ls0);  atomicAdd(&s_sum[4*cg+1], ls1);
    atomicAdd(&s_sum[4*cg+2], ls2);  atomicAdd(&s_sum[4*cg+3], ls3);
    atomicAdd(&s_sum2[4*cg+0], lq0); atomicAdd(&s_sum2[4*cg+1], lq1);
    atomicAdd(&s_sum2[4*cg+2], lq2); atomicAdd(&s_sum2[4*cg+3], lq3);
    __syncthreads();
    if (tid < D) {
        atomicAdd(&g_colsum[tid],  s_sum[tid]);
        atomicAdd(&g_colsum2[tid], s_sum2[tid]);
    }
}

// ---------------- 4. finalize (params folded in, fp16 h input) --------------
__global__ void finalize_kernel(const float4* __restrict__ feat,
                                float4* __restrict__ out,
                                const float* __restrict__ gamma,
                                const float* __restrict__ beta,
                                float inv_n, int n4) {
    __shared__ float ssc[D], ssh[D];
    if (threadIdx.x < D) {
        int j = threadIdx.x;
        float mu  = g_colsum[j]  * inv_n;
        float var = g_colsum2[j] * inv_n - mu * mu;
        float sc  = gamma[j] * rsqrtf(var + EPSV);
        ssc[j] = sc;
        ssh[j] = beta[j] - mu * sc;
    }
    __syncthreads();
    const uint2* H = (const uint2*)g_hH;
    for (int i = blockIdx.x * blockDim.x + threadIdx.x; i < n4;
         i += gridDim.x * blockDim.x) {
        int c = i & (D4 - 1);
        uint2 hv = H[i];
        float2 h0 = __half22float2(*(__half2*)&hv.x);
        float2 h1 = __half22float2(*(__half2*)&hv.y);
        float4 f = feat[i];
        float4 sc = *(float4*)&ssc[c * 4];
        float4 sh = *(float4*)&ssh[c * 4];
        float4 o;
        o.x = f.x + fmaxf(h0.x * sc.x + sh.x, 0.f);
        o.y = f.y + fmaxf(h0.y * sc.y + sh.y, 0.f);
        o.z = f.z + fmaxf(h1.x * sc.z + sh.z, 0.f);
        o.w = f.w + fmaxf(h1.y * sc.w + sh.w, 0.f);
        out[i] = o;
    }
}

// ---------------- launch -----------------------------------------------------
extern "C" void kernel_launch(void* const* d_in, const int* in_sizes, int n_in,
                              void* d_out, int out_size) {
    const float* feature = (const float*)d_in[0];
    const int*   src     = (const int*)d_in[1];
    const int*   dst     = (const int*)d_in[2];
    const float* W       = (const float*)d_in[3];
    const float* b       = (const float*)d_in[4];
    const float* gamma   = (const float*)d_in[5];
    const float* beta    = (const float*)d_in[6];
    float*       out     = (float*)d_out;

    int n  = in_sizes[0] / D;
    int e  = in_sizes[1];
    int n4 = n * D4;

    int tot8  = n * D / 8;
    int scatB = ((e + 3) / 4 + 255) / 256;
    int halfB = (tot8 + 255) / 256;
    int wB    = (D * D / 8 + 255) / 256;

    build_kernel<<<scatB + halfB + wB + 1, 256>>>(src, dst, e, (const float4*)feature,
                                                  tot8, (const float4*)W, scatB, halfB, wB);

    gather_mean_kernel<<<(n * 32 + 255) / 256, 256>>>(n);

    static const int GEMM_SMEM = 69632 + 1024;           // 70656
    cudaFuncSetAttribute(gemm_kernel, cudaFuncAttributeMaxDynamicSharedMemorySize, GEMM_SMEM);
    gemm_kernel<<<(n + 127) / 128, 256, GEMM_SMEM>>>(b, n);

    finalize_kernel<<<(n4 + 255) / 256, 256>>>((const float4*)feature, (float4*)out,
                                               gamma, beta, 1.f / (float)n, n4);
}

// round 16
// speedup vs baseline: 1.7205x; 1.7205x over previous
#include <cuda_runtime.h>
#include <cuda_fp16.h>
#include <mma.h>

using namespace nvcuda;

#define D       128
#define D4      32
#define CAP     128         // bucket capacity; Poisson(32) => P(deg>128) ~ 1e-40
#define N_MAX   100000
#define E_MAX   3200000
#define EPSV    1e-5f

#define SAPAD   136         // half stride for smem tiles (272B: conflict-free ldmatrix)
#define SHPAD   132         // float stride for fp32 result tile

// ---------------- scratch (static device globals) --------------------------
__device__ int    g_cnt[N_MAX];
__device__ int    g_slot[(size_t)N_MAX * CAP];
__device__ __half g_featH[(size_t)N_MAX * D];
__device__ __half g_meanH[(size_t)N_MAX * D];
__device__ __half g_WH[D * D];
__device__ __half g_hH[(size_t)N_MAX * D];
__device__ float  g_colsum[D];
__device__ float  g_colsum2[D];

// ---------------- 1. zero accumulators -------------------------------------
__global__ void zero_kernel(int n) {
    int i = blockIdx.x * blockDim.x + threadIdx.x;
    if (i < n) g_cnt[i] = 0;
    if (i < D) { g_colsum[i] = 0.f; g_colsum2[i] = 0.f; }
}

// ---------------- 2. fused build: bucket scatter + feat->fp16 + W->fp16 ----
__global__ void build_kernel(const int* __restrict__ src,
                             const int* __restrict__ dst, int e,
                             const float4* __restrict__ feat, int tot8,
                             const float4* __restrict__ W,
                             int scatB, int halfB) {
    int b = blockIdx.x, tid = threadIdx.x;
    if (b < scatB) {
        int base = (b * 256 + tid) * 4;
        if (base + 3 < e) {
            int4 d = *(const int4*)(dst + base);
            int4 s = *(const int4*)(src + base);
            int p;
            p = atomicAdd(&g_cnt[d.x], 1); if (p < CAP) g_slot[(size_t)d.x * CAP + p] = s.x;
            p = atomicAdd(&g_cnt[d.y], 1); if (p < CAP) g_slot[(size_t)d.y * CAP + p] = s.y;
            p = atomicAdd(&g_cnt[d.z], 1); if (p < CAP) g_slot[(size_t)d.z * CAP + p] = s.z;
            p = atomicAdd(&g_cnt[d.w], 1); if (p < CAP) g_slot[(size_t)d.w * CAP + p] = s.w;
        } else {
            for (int j = base; j < e; j++) {
                int dd = dst[j];
                int p = atomicAdd(&g_cnt[dd], 1);
                if (p < CAP) g_slot[(size_t)dd * CAP + p] = src[j];
            }
        }
    } else if (b < scatB + halfB) {
        int i = (b - scatB) * 256 + tid;            // one per 8 floats
        if (i < tot8) {
            float4 a = feat[2 * i], c = feat[2 * i + 1];
            __half2 h0 = __floats2half2_rn(a.x, a.y);
            __half2 h1 = __floats2half2_rn(a.z, a.w);
            __half2 h2 = __floats2half2_rn(c.x, c.y);
            __half2 h3 = __floats2half2_rn(c.z, c.w);
            uint4 o;
            o.x = *(unsigned*)&h0; o.y = *(unsigned*)&h1;
            o.z = *(unsigned*)&h2; o.w = *(unsigned*)&h3;
            ((uint4*)g_featH)[i] = o;
        }
    } else {
        int i = (b - scatB - halfB) * 256 + tid;    // one per 8 W floats
        if (i < D * D / 8) {
            float4 a = W[2 * i], c = W[2 * i + 1];
            __half2 h0 = __floats2half2_rn(a.x, a.y);
            __half2 h1 = __floats2half2_rn(a.z, a.w);
            __half2 h2 = __floats2half2_rn(c.x, c.y);
            __half2 h3 = __floats2half2_rn(c.z, c.w);
            uint4 o;
            o.x = *(unsigned*)&h0; o.y = *(unsigned*)&h1;
            o.z = *(unsigned*)&h2; o.w = *(unsigned*)&h3;
            ((uint4*)g_WH)[i] = o;
        }
    }
}

// ---------------- 3. per-node mean aggregation (1 warp/node, 2 edges/iter) --
__global__ void gather_mean_kernel(int n) {
    int gw   = (blockIdx.x * blockDim.x + threadIdx.x) >> 5;
    int lane = threadIdx.x & 31;
    if (gw >= n) return;
    int deg = g_cnt[gw];
    if (deg > CAP) deg = CAP;
    size_t base = (size_t)gw * CAP;
    int half = lane >> 4;           // edge parity
    int sub  = lane & 15;           // position within row (16 x 16B)
    const uint4* F = (const uint4*)g_featH;    // 16 uint4 per row
    float a0=0.f,a1=0.f,a2=0.f,a3=0.f,a4=0.f,a5=0.f,a6=0.f,a7=0.f;
    for (int i = half; i < deg; i += 2) {
        int sr = g_slot[base + i];
        uint4 v = __ldg(&F[(size_t)sr * 16 + sub]);
        float2 f0 = __half22float2(*(__half2*)&v.x);
        float2 f1 = __half22float2(*(__half2*)&v.y);
        float2 f2 = __half22float2(*(__half2*)&v.z);
        float2 f3 = __half22float2(*(__half2*)&v.w);
        a0 += f0.x; a1 += f0.y; a2 += f1.x; a3 += f1.y;
        a4 += f2.x; a5 += f2.y; a6 += f3.x; a7 += f3.y;
    }
    a0 += __shfl_xor_sync(0xffffffffu, a0, 16);
    a1 += __shfl_xor_sync(0xffffffffu, a1, 16);
    a2 += __shfl_xor_sync(0xffffffffu, a2, 16);
    a3 += __shfl_xor_sync(0xffffffffu, a3, 16);
    a4 += __shfl_xor_sync(0xffffffffu, a4, 16);
    a5 += __shfl_xor_sync(0xffffffffu, a5, 16);
    a6 += __shfl_xor_sync(0xffffffffu, a6, 16);
    a7 += __shfl_xor_sync(0xffffffffu, a7, 16);
    if (half == 0) {
        float inv = 1.f / fmaxf((float)deg, 1.f);
        __half2 o0 = __floats2half2_rn(a0 * inv, a1 * inv);
        __half2 o1 = __floats2half2_rn(a2 * inv, a3 * inv);
        __half2 o2 = __floats2half2_rn(a4 * inv, a5 * inv);
        __half2 o3 = __floats2half2_rn(a6 * inv, a7 * inv);
        uint4 o;
        o.x = *(unsigned*)&o0; o.y = *(unsigned*)&o1;
        o.z = *(unsigned*)&o2; o.w = *(unsigned*)&o3;
        ((uint4*)g_meanH)[(size_t)gw * 16 + sub] = o;
    }
}

// ---------------- 4. wmma GEMM h = mean @ W + b, fused stats, fp16 h out ----
// block = 256 thr (8 warps), tile = 128 rows x 128 cols.
// warp w: rows (w>>1)*32 .. +32, cols (w&1)*64 .. +64 -> 2x4 accumulator frags.
__global__ void __launch_bounds__(256) gemm_kernel(const float* __restrict__ bias, int n) {
    extern __shared__ char smem[];
    __half* sW = (__half*)smem;                           // 128 x SAPAD (34816 B)
    __half* sA = (__half*)(smem + 34816);                 // 128 x SAPAD (34816 B)
    float*  sH = (float*)smem;                            // 128 x SHPAD fp32 (67584 B, aliases)
    float*  s_sum  = (float*)(smem + 69632);
    float*  s_sum2 = (float*)(smem + 69632 + 512);

    int tid = threadIdx.x;
    int row0 = blockIdx.x * 128;

    #pragma unroll
    for (int t = tid; t < 128 * 16; t += 256) {
        int r = t >> 4, c = t & 15;
        ((uint4*)(sW + r * SAPAD))[c] = ((const uint4*)g_WH)[r * 16 + c];
    }
    uint4 z4; z4.x = z4.y = z4.z = z4.w = 0u;
    #pragma unroll
    for (int t = tid; t < 128 * 16; t += 256) {
        int r = t >> 4, c = t & 15;
        ((uint4*)(sA + r * SAPAD))[c] =
            (row0 + r < n) ? ((const uint4*)g_meanH)[(size_t)(row0 + r) * 16 + c] : z4;
    }
    if (tid < D) { s_sum[tid] = 0.f; s_sum2[tid] = 0.f; }
    __syncthreads();

    int wid = tid >> 5;
    int wr = wid >> 1;                                    // 0..3 -> 32-row strip
    int wc = wid & 1;                                     // 0..1 -> 64-col half
    wmma::fragment<wmma::accumulator, 16, 16, 16, float> acc[2][4];
    #pragma unroll
    for (int i = 0; i < 2; i++)
        #pragma unroll
        for (int j = 0; j < 4; j++) wmma::fill_fragment(acc[i][j], 0.f);

    #pragma unroll
    for (int k = 0; k < D; k += 16) {
        wmma::fragment<wmma::matrix_a, 16, 16, 16, __half, wmma::row_major> fa[2];
        #pragma unroll
        for (int i = 0; i < 2; i++)
            wmma::load_matrix_sync(fa[i], sA + (wr * 32 + i * 16) * SAPAD + k, SAPAD);
        #pragma unroll
        for (int j = 0; j < 4; j++) {
            wmma::fragment<wmma::matrix_b, 16, 16, 16, __half, wmma::row_major> fb;
            wmma::load_matrix_sync(fb, sW + k * SAPAD + wc * 64 + j * 16, SAPAD);
            wmma::mma_sync(acc[0][j], fa[0], fb, acc[0][j]);
            wmma::mma_sync(acc[1][j], fa[1], fb, acc[1][j]);
        }
    }
    __syncthreads();                                      // all reads of sW/sA done
    #pragma unroll
    for (int i = 0; i < 2; i++)
        #pragma unroll
        for (int j = 0; j < 4; j++)
            wmma::store_matrix_sync(sH + (wr * 32 + i * 16) * SHPAD + wc * 64 + j * 16,
                                    acc[i][j], SHPAD, wmma::mem_row_major);
    __syncthreads();

    // epilogue: 256 threads, each handles 16 rows x 4 cols
    int cg = tid & 31, rg = tid >> 5;                     // rg 0..7
    float4 bb = ((const float4*)bias)[cg];
    float ls0=0.f, ls1=0.f, ls2=0.f, ls3=0.f;
    float lq0=0.f, lq1=0.f, lq2=0.f, lq3=0.f;
    #pragma unroll
    for (int i = 0; i < 16; i++) {
        int r = row0 + rg * 16 + i;
        if (r < n) {
            float4 h = *(float4*)&sH[(rg * 16 + i) * SHPAD + cg * 4];
            float x0 = h.x + bb.x, x1 = h.y + bb.y, x2 = h.z + bb.z, x3 = h.w + bb.w;
            ls0 += x0; ls1 += x1; ls2 += x2; ls3 += x3;
            lq0 += x0*x0; lq1 += x1*x1; lq2 += x2*x2; lq3 += x3*x3;
            __half2 p0 = __floats2half2_rn(x0, x1);
            __half2 p1 = __floats2half2_rn(x2, x3);
            uint2 o; o.x = *(unsigned*)&p0; o.y = *(unsigned*)&p1;
            ((uint2*)g_hH)[(size_t)r * 32 + cg] = o;
        }
    }
    atomicAdd(&s_sum[4*cg+0], ls0);  atomicAdd(&s_sum[4*cg+1], ls1);
    atomicAdd(&s_sum[4*cg+2], ls2);  atomicAdd(&s_sum[4*cg+3], ls3);
    atomicAdd(&s_sum2[4*cg+0], lq0); atomicAdd(&s_sum2[4*cg+1], lq1);
    atomicAdd(&s_sum2[4*cg+2], lq2); atomicAdd(&s_sum2[4*cg+3], lq3);
    __syncthreads();
    if (tid < D) {
        atomicAdd(&g_colsum[tid],  s_sum[tid]);
        atomicAdd(&g_colsum2[tid], s_sum2[tid]);
    }
}

// ---------------- 5. finalize: 2 float4 items per thread for load MLP -------
__global__ void finalize_kernel(const float4* __restrict__ feat,
                                float4* __restrict__ out,
                                const float* __restrict__ gamma,
                                const float* __restrict__ beta,
                                float inv_n, int n4) {
    __shared__ float ssc[D], ssh[D];
    if (threadIdx.x < D) {
        int j = threadIdx.x;
        float mu  = g_colsum[j]  * inv_n;
        float var = g_colsum2[j] * inv_n - mu * mu;
        float sc  = gamma[j] * rsqrtf(var + EPSV);
        ssc[j] = sc;
        ssh[j] = beta[j] - mu * sc;
    }
    __syncthreads();
    const uint2* H = (const uint2*)g_hH;
    int stride = gridDim.x * blockDim.x;                  // items per half-pass
    for (int i0 = blockIdx.x * blockDim.x + threadIdx.x; i0 < n4; i0 += 2 * stride) {
        int i1 = i0 + stride;
        bool has1 = (i1 < n4);
        // batch all independent loads first (4-5 LDGs in flight)
        uint2  hv0 = H[i0];
        float4 f0  = feat[i0];
        uint2  hv1 = has1 ? H[i1] : make_uint2(0u, 0u);
        float4 f1  = has1 ? feat[i1] : make_float4(0.f, 0.f, 0.f, 0.f);

        {
            int c = i0 & (D4 - 1);
            float2 h0 = __half22float2(*(__half2*)&hv0.x);
            float2 h1 = __half22float2(*(__half2*)&hv0.y);
            float4 sc = *(float4*)&ssc[c * 4];
            float4 sh = *(float4*)&ssh[c * 4];
            float4 o;
            o.x = f0.x + fmaxf(h0.x * sc.x + sh.x, 0.f);
            o.y = f0.y + fmaxf(h0.y * sc.y + sh.y, 0.f);
            o.z = f0.z + fmaxf(h1.x * sc.z + sh.z, 0.f);
            o.w = f0.w + fmaxf(h1.y * sc.w + sh.w, 0.f);
            out[i0] = o;
        }
        if (has1) {
            int c = i1 & (D4 - 1);
            float2 h0 = __half22float2(*(__half2*)&hv1.x);
            float2 h1 = __half22float2(*(__half2*)&hv1.y);
            float4 sc = *(float4*)&ssc[c * 4];
            float4 sh = *(float4*)&ssh[c * 4];
            float4 o;
            o.x = f1.x + fmaxf(h0.x * sc.x + sh.x, 0.f);
            o.y = f1.y + fmaxf(h0.y * sc.y + sh.y, 0.f);
            o.z = f1.z + fmaxf(h1.x * sc.z + sh.z, 0.f);
            o.w = f1.w + fmaxf(h1.y * sc.w + sh.w, 0.f);
            out[i1] = o;
        }
    }
}

// ---------------- launch -----------------------------------------------------
extern "C" void kernel_launch(void* const* d_in, const int* in_sizes, int n_in,
                              void* d_out, int out_size) {
    const float* feature = (const float*)d_in[0];
    const int*   src     = (const int*)d_in[1];
    const int*   dst     = (const int*)d_in[2];
    const float* W       = (const float*)d_in[3];
    const float* b       = (const float*)d_in[4];
    const float* gamma   = (const float*)d_in[5];
    const float* beta    = (const float*)d_in[6];
    float*       out     = (float*)d_out;

    int n  = in_sizes[0] / D;
    int e  = in_sizes[1];
    int n4 = n * D4;

    int tot8  = n * D / 8;
    int scatB = ((e + 3) / 4 + 255) / 256;
    int halfB = (tot8 + 255) / 256;
    int wB    = (D * D / 8 + 255) / 256;

    zero_kernel<<<(n + 255) / 256, 256>>>(n);
    build_kernel<<<scatB + halfB + wB, 256>>>(src, dst, e, (const float4*)feature,
                                              tot8, (const float4*)W, scatB, halfB);

    gather_mean_kernel<<<(n * 32 + 255) / 256, 256>>>(n);

    static const int GEMM_SMEM = 69632 + 1024;           // 70656
    cudaFuncSetAttribute(gemm_kernel, cudaFuncAttributeMaxDynamicSharedMemorySize, GEMM_SMEM);
    gemm_kernel<<<(n + 127) / 128, 256, GEMM_SMEM>>>(b, n);

    int finB = (n4 / 2 + 255) / 256;                     // 2 items per thread
    finalize_kernel<<<finB, 256>>>((const float4*)feature, (float4*)out,
                                   gamma, beta, 1.f / (float)n, n4);
}